// round 2
// baseline (speedup 1.0000x reference)
#include <cuda_runtime.h>
#include <cuda_bf16.h>
#include <mma.h>
using namespace nvcuda;

#define NBATCH 2048
#define NN 1024
#define NP 16
#define SSTRIDE 18433        // 1024 ablate + 1 pc2 + 1024 neuron + 16384 peptide
#define PC2_OFF 1024
#define NEU_OFF 1025
#define PEP_OFF 2049
#define DT_F (1.0f/120.0f)

#define SM_PEP_STRIDE 12     // 8 peptides + 4 pad: 48B row -> 16B-aligned LDS.128,
                             // conflict-free within 8-thread phases (12 mod 32 pattern)

// Scratch (allocation-free rule: __device__ globals)
__device__ __nv_bfloat16 g_fir16[(size_t)NBATCH*NN];
__device__ float g_dsyn[(size_t)NBATCH*NN];

// ---------------------------------------------------------------------------
// K1: firing = clip(-(relu(neuron)*ablate + 0.01)*log1p(-noise), 0, 10)
//     also emits bf16 copy for the GEMM and copies ablate/pc2 into state_new.
// ---------------------------------------------------------------------------
__global__ __launch_bounds__(256) void k_firing(
    const float* __restrict__ state, const float* __restrict__ noise_u,
    float* __restrict__ out_firing, float* __restrict__ out_state)
{
    int idx = blockIdx.x * 256 + threadIdx.x;   // exactly NBATCH*NN threads
    int row = idx >> 10;
    int n   = idx & (NN - 1);
    size_t base = (size_t)row * SSTRIDE;
    float ab    = state[base + n];
    float ne    = state[base + NEU_OFF + n];
    float noise = noise_u[idx];
    float f0  = fmaxf(ne, 0.0f) * ab;
    float fir = -(f0 + 0.01f) * log1pf(-noise);
    fir = fminf(fmaxf(fir, 0.0f), 10.0f);
    out_firing[idx] = fir;
    g_fir16[idx] = __float2bfloat16(fir);
    out_state[base + n] = ab;                       // ablate passthrough
    if (n == 0) out_state[base + PC2_OFF] = state[base + PC2_OFF];
}

// ---------------------------------------------------------------------------
// K2: g_dsyn[2048,1024] = firing_bf16[2048,1024] @ synapse[1024,1024]
// bf16 wmma, 128x128x32 tiles, 8 warps (4x2), warp tile 32x64.
// synapse converted fp32->bf16 while staging to SMEM (synapse fits in L2).
// ---------------------------------------------------------------------------
__global__ __launch_bounds__(256) void k_gemm(const float* __restrict__ Bsrc)
{
    __shared__ __nv_bfloat16 As[128][40];   // 128x32 tile, +8 pad
    __shared__ __nv_bfloat16 Bs[32][136];   // 32x128 tile, +8 pad
    const int bm = blockIdx.y, bn = blockIdx.x;
    const int tid = threadIdx.x;
    const int wid = tid >> 5;
    const int wm = wid >> 1;   // 0..3 -> 32-row slab
    const int wn = wid & 1;    // 0..1 -> 64-col slab

    wmma::fragment<wmma::accumulator,16,16,16,float> acc[2][4];
    #pragma unroll
    for (int i = 0; i < 2; i++)
        #pragma unroll
        for (int j = 0; j < 4; j++) wmma::fill_fragment(acc[i][j], 0.0f);

    for (int k0 = 0; k0 < NN; k0 += 32) {
        // A tile: 128x32 bf16 = 2048 u32 loads
        #pragma unroll
        for (int j = 0; j < 8; j++) {
            int idx = tid + j*256;
            int r = idx >> 4, c = idx & 15;
            unsigned v = *(const unsigned*)(g_fir16 + (size_t)(bm*128 + r)*NN + k0 + c*2);
            *(unsigned*)(&As[r][c*2]) = v;
        }
        // B tile: 32x128 fp32 -> bf16
        #pragma unroll
        for (int j = 0; j < 4; j++) {
            int idx = tid + j*256;
            int r = idx >> 5, c = idx & 31;
            float4 v = *(const float4*)(Bsrc + (size_t)(k0 + r)*NN + bn*128 + c*4);
            __nv_bfloat162 lo = __floats2bfloat162_rn(v.x, v.y);
            __nv_bfloat162 hi = __floats2bfloat162_rn(v.z, v.w);
            *(__nv_bfloat162*)(&Bs[r][c*4])     = lo;
            *(__nv_bfloat162*)(&Bs[r][c*4 + 2]) = hi;
        }
        __syncthreads();
        #pragma unroll
        for (int kk = 0; kk < 32; kk += 16) {
            wmma::fragment<wmma::matrix_a,16,16,16,__nv_bfloat16,wmma::row_major> af[2];
            wmma::fragment<wmma::matrix_b,16,16,16,__nv_bfloat16,wmma::row_major> bf[4];
            #pragma unroll
            for (int i = 0; i < 2; i++)
                wmma::load_matrix_sync(af[i], &As[wm*32 + i*16][kk], 40);
            #pragma unroll
            for (int j = 0; j < 4; j++)
                wmma::load_matrix_sync(bf[j], &Bs[kk][wn*64 + j*16], 136);
            #pragma unroll
            for (int i = 0; i < 2; i++)
                #pragma unroll
                for (int j = 0; j < 4; j++)
                    wmma::mma_sync(acc[i][j], af[i], bf[j], acc[i][j]);
        }
        __syncthreads();
    }
    #pragma unroll
    for (int i = 0; i < 2; i++)
        #pragma unroll
        for (int j = 0; j < 4; j++)
            wmma::store_matrix_sync(
                g_dsyn + (size_t)(bm*128 + wm*32 + i*16)*NN + bn*128 + wn*64 + j*16,
                acc[i][j], NN, wmma::mem_row_major);
}

// ---------------------------------------------------------------------------
// K3: per batch-row, TWO PASSES of 8 peptide channels each (fits 48KB static
// smem -> no cudaFuncSetAttribute needed). Stage half the peptide row in SMEM
// (stride-12 padded), do the 32x32 periodic 5-point laplacian per channel,
// write pep_new, accumulate pep.action per neuron across passes, then
// integrate neuron_new at the end of pass 1.
// ---------------------------------------------------------------------------
__global__ __launch_bounds__(256) void k_update(
    const float* __restrict__ state, const float* __restrict__ firing,
    const float* __restrict__ u, const float* __restrict__ D,
    const float* __restrict__ prod, const float* __restrict__ decay,
    const float* __restrict__ act, const float* __restrict__ ndecay,
    const float* __restrict__ input_layer, float* __restrict__ out_state)
{
    __shared__ float pep_s[NN * SM_PEP_STRIDE];   // 49152 bytes = 48KB

    const int row = blockIdx.x;
    const int t = threadIdx.x;
    const size_t base = (size_t)row * SSTRIDE;
    const float* pep_g = state + base + PEP_OFF;
    float* outp = out_state + base + PEP_OFF;

    const float ndec = fabsf(ndecay[0]);
    const float uval = u[row];
    const float pc2  = state[base + PC2_OFF];

    float pepsum[4] = {0.0f, 0.0f, 0.0f, 0.0f};
    float fir_r[4];

    #pragma unroll
    for (int pass = 0; pass < 2; pass++) {
        if (pass) __syncthreads();   // pass-0 compute done before restaging
        // Stage 8 channels of the peptide row (scalar global: base only 4B aligned)
        for (int i = t; i < NN * 8; i += 256) {
            int n = i >> 3, p = i & 7;
            pep_s[n * SM_PEP_STRIDE + p] = pep_g[n * NP + pass * 8 + p];
        }
        __syncthreads();

        #pragma unroll
        for (int k = 0; k < 4; k++) {
            const int n = t + k*256;
            const int y = n >> 5, x = n & 31;
            const int nu = (((y+31)&31) << 5) | x;
            const int nd = (((y+1)&31)  << 5) | x;
            const int nl = (y << 5) | ((x+31)&31);
            const int nr = (y << 5) | ((x+1)&31);
            if (pass == 0) fir_r[k] = firing[row*NN + n];
            const float fir = fir_r[k];
            const float* Cn = pep_s + n *SM_PEP_STRIDE;
            const float* Un = pep_s + nu*SM_PEP_STRIDE;
            const float* Dn = pep_s + nd*SM_PEP_STRIDE;
            const float* Ln = pep_s + nl*SM_PEP_STRIDE;
            const float* Rn = pep_s + nr*SM_PEP_STRIDE;
            #pragma unroll
            for (int q = 0; q < 2; q++) {
                const int po = pass*8 + q*4;   // peptide channel offset
                float4 c  = *(const float4*)(Cn + q*4);
                float4 a4 = *(const float4*)(Un + q*4);
                float4 b4 = *(const float4*)(Dn + q*4);
                float4 l4 = *(const float4*)(Ln + q*4);
                float4 r4 = *(const float4*)(Rn + q*4);
                float4 dd = *(const float4*)(D     + po);   // uniform, L1-resident
                float4 pr = *(const float4*)(prod  + po);
                float4 de = *(const float4*)(decay + po);
                float4 aa = *(const float4*)(act   + po);
                float ddx = fabsf(dd.x), ddy = fabsf(dd.y), ddz = fabsf(dd.z), ddw = fabsf(dd.w);
                float prx = fabsf(pr.x), pry = fabsf(pr.y), prz = fabsf(pr.z), prw = fabsf(pr.w);
                float dex = fabsf(de.x), dey = fabsf(de.y), dez = fabsf(de.z), dew = fabsf(de.w);
                float lx = a4.x + b4.x + l4.x + r4.x - 4.0f*c.x;
                float ly = a4.y + b4.y + l4.y + r4.y - 4.0f*c.y;
                float lz = a4.z + b4.z + l4.z + r4.z - 4.0f*c.z;
                float lw = a4.w + b4.w + l4.w + r4.w - 4.0f*c.w;
                // scalar stores: peptide region only 4B aligned (row stride odd)
                outp[n*NP + po + 0] = c.x + DT_F*(prx*fir - dex*c.x + ddx*lx);
                outp[n*NP + po + 1] = c.y + DT_F*(pry*fir - dey*c.y + ddy*ly);
                outp[n*NP + po + 2] = c.z + DT_F*(prz*fir - dez*c.z + ddz*lz);
                outp[n*NP + po + 3] = c.w + DT_F*(prw*fir - dew*c.w + ddw*lw);
                pepsum[k] += c.x*aa.x + c.y*aa.y + c.z*aa.z + c.w*aa.w;
            }
            if (pass == 1) {
                const float ab = state[base + n];
                const float ne = state[base + NEU_OFF + n] * ab;
                const float dn = pepsum[k]*pc2 + g_dsyn[row*NN + n]
                               - ne*ndec + input_layer[n]*uval;
                out_state[base + NEU_OFF + n] = (ne + dn*DT_F) * ab;
            }
        }
    }
}

// ---------------------------------------------------------------------------
// Inputs (metadata order): u, state, noise_u, D, pep_prod_rate, pep_decay_rate,
// pep_action, synapse_matrix, neuron_decay, input_layer.
// Output: [firing (2048*1024) | state_new (2048*18433)] fp32.
// ---------------------------------------------------------------------------
extern "C" void kernel_launch(void* const* d_in, const int* in_sizes, int n_in,
                              void* d_out, int out_size)
{
    const float* u       = (const float*)d_in[0];
    const float* state   = (const float*)d_in[1];
    const float* noise_u = (const float*)d_in[2];
    const float* D       = (const float*)d_in[3];
    const float* prod    = (const float*)d_in[4];
    const float* decay   = (const float*)d_in[5];
    const float* act     = (const float*)d_in[6];
    const float* syn     = (const float*)d_in[7];
    const float* ndec    = (const float*)d_in[8];
    const float* inl     = (const float*)d_in[9];

    float* out        = (float*)d_out;
    float* out_firing = out;
    float* out_state  = out + (size_t)NBATCH*NN;

    k_firing<<<(NBATCH*NN)/256, 256>>>(state, noise_u, out_firing, out_state);

    dim3 gg(NN/128, NBATCH/128);   // 8 x 16 CTAs
    k_gemm<<<gg, 256>>>(syn);

    k_update<<<NBATCH, 256>>>(
        state, out_firing, u, D, prod, decay, act, ndec, inl, out_state);
}

// round 3
// speedup vs baseline: 1.5050x; 1.5050x over previous
#include <cuda_runtime.h>
#include <cuda_bf16.h>
#include <mma.h>
using namespace nvcuda;

#define NBATCH 2048
#define NN 1024
#define NP 16
#define SSTRIDE 18433        // 1024 ablate + 1 pc2 + 1024 neuron + 16384 peptide
#define PC2_OFF 1024
#define NEU_OFF 1025
#define PEP_OFF 2049
#define DT_F (1.0f/120.0f)

// Scratch (allocation-free rule: __device__ globals)
__device__ __nv_bfloat16 g_fir16[(size_t)NBATCH*NN];
__device__ __nv_bfloat16 g_syn16[(size_t)NN*NN];
__device__ float g_dsyn[(size_t)NBATCH*NN];

// ---------------------------------------------------------------------------
// K0: one-time synapse fp32 -> bf16 (removes 16x redundant conversion in gemm)
// ---------------------------------------------------------------------------
__global__ __launch_bounds__(256) void k_cvt(const float* __restrict__ syn)
{
    int i = blockIdx.x * 256 + threadIdx.x;          // NN*NN/4 threads
    float4 v = ((const float4*)syn)[i];
    __nv_bfloat162 lo = __floats2bfloat162_rn(v.x, v.y);
    __nv_bfloat162 hi = __floats2bfloat162_rn(v.z, v.w);
    ((__nv_bfloat162*)g_syn16)[i*2]     = lo;
    ((__nv_bfloat162*)g_syn16)[i*2 + 1] = hi;
}

// ---------------------------------------------------------------------------
// K1: firing = clip(-(relu(neuron)*ablate + 0.01)*log1p(-noise), 0, 10)
//     also emits bf16 copy for the GEMM and copies ablate/pc2 into state_new.
// ---------------------------------------------------------------------------
__global__ __launch_bounds__(256) void k_firing(
    const float* __restrict__ state, const float* __restrict__ noise_u,
    float* __restrict__ out_firing, float* __restrict__ out_state)
{
    int idx = blockIdx.x * 256 + threadIdx.x;   // exactly NBATCH*NN threads
    int row = idx >> 10;
    int n   = idx & (NN - 1);
    size_t base = (size_t)row * SSTRIDE;
    float ab    = state[base + n];
    float ne    = state[base + NEU_OFF + n];
    float noise = noise_u[idx];
    float f0  = fmaxf(ne, 0.0f) * ab;
    float fir = -(f0 + 0.01f) * log1pf(-noise);
    fir = fminf(fmaxf(fir, 0.0f), 10.0f);
    out_firing[idx] = fir;
    g_fir16[idx] = __float2bfloat16(fir);
    out_state[base + n] = ab;                       // ablate passthrough
    if (n == 0) out_state[base + PC2_OFF] = state[base + PC2_OFF];
}

// ---------------------------------------------------------------------------
// K2: g_dsyn[2048,1024] = firing_bf16 @ synapse_bf16
// 128x128x32 tiles, 8 warps (4x2), warp tile 32x64, register-prefetched
// double buffering of the next K tile during compute.
// ---------------------------------------------------------------------------
__global__ __launch_bounds__(256) void k_gemm()
{
    __shared__ __nv_bfloat16 As[128][48];   // stride 96B (16B multiple)
    __shared__ __nv_bfloat16 Bs[32][144];   // stride 288B (16B multiple)
    const int bm = blockIdx.y, bn = blockIdx.x;
    const int tid = threadIdx.x;
    const int wid = tid >> 5;
    const int wm = wid >> 1;   // 0..3 -> 32-row slab
    const int wn = wid & 1;    // 0..1 -> 64-col slab

    // A-tile thread map: 512 uint4 (128 rows x 4), 2 per thread
    const int ar0 = (tid      ) >> 2, ac0 = (tid      ) & 3;
    const int ar1 = (tid + 256) >> 2, ac1 = (tid + 256) & 3;
    // B-tile thread map: 512 uint4 (32 rows x 16), 2 per thread
    const int br0 = (tid      ) >> 4, bc0 = (tid      ) & 15;
    const int br1 = (tid + 256) >> 4, bc1 = (tid + 256) & 15;

    const __nv_bfloat16* Ag = g_fir16 + (size_t)bm*128*NN;
    const __nv_bfloat16* Bg = g_syn16 + bn*128;

    wmma::fragment<wmma::accumulator,16,16,16,float> acc[2][4];
    #pragma unroll
    for (int i = 0; i < 2; i++)
        #pragma unroll
        for (int j = 0; j < 4; j++) wmma::fill_fragment(acc[i][j], 0.0f);

    uint4 ra0, ra1, rb0, rb1;
    // prefetch k0 = 0
    ra0 = *(const uint4*)(Ag + (size_t)ar0*NN + ac0*8);
    ra1 = *(const uint4*)(Ag + (size_t)ar1*NN + ac1*8);
    rb0 = *(const uint4*)(Bg + (size_t)br0*NN + bc0*8);
    rb1 = *(const uint4*)(Bg + (size_t)br1*NN + bc1*8);

    for (int k0 = 0; k0 < NN; k0 += 32) {
        *(uint4*)(&As[ar0][ac0*8]) = ra0;
        *(uint4*)(&As[ar1][ac1*8]) = ra1;
        *(uint4*)(&Bs[br0][bc0*8]) = rb0;
        *(uint4*)(&Bs[br1][bc1*8]) = rb1;
        __syncthreads();
        if (k0 + 32 < NN) {   // prefetch next K tile while mma runs
            ra0 = *(const uint4*)(Ag + (size_t)ar0*NN + k0+32 + ac0*8);
            ra1 = *(const uint4*)(Ag + (size_t)ar1*NN + k0+32 + ac1*8);
            rb0 = *(const uint4*)(Bg + (size_t)(k0+32+br0)*NN + bc0*8);
            rb1 = *(const uint4*)(Bg + (size_t)(k0+32+br1)*NN + bc1*8);
        }
        #pragma unroll
        for (int kk = 0; kk < 32; kk += 16) {
            wmma::fragment<wmma::matrix_a,16,16,16,__nv_bfloat16,wmma::row_major> af[2];
            wmma::fragment<wmma::matrix_b,16,16,16,__nv_bfloat16,wmma::row_major> bf[4];
            #pragma unroll
            for (int i = 0; i < 2; i++)
                wmma::load_matrix_sync(af[i], &As[wm*32 + i*16][kk], 48);
            #pragma unroll
            for (int j = 0; j < 4; j++)
                wmma::load_matrix_sync(bf[j], &Bs[kk][wn*64 + j*16], 144);
            #pragma unroll
            for (int i = 0; i < 2; i++)
                #pragma unroll
                for (int j = 0; j < 4; j++)
                    wmma::mma_sync(acc[i][j], af[i], bf[j], acc[i][j]);
        }
        __syncthreads();
    }
    #pragma unroll
    for (int i = 0; i < 2; i++)
        #pragma unroll
        for (int j = 0; j < 4; j++)
            wmma::store_matrix_sync(
                g_dsyn + (size_t)(bm*128 + wm*32 + i*16)*NN + bn*128 + wn*64 + j*16,
                acc[i][j], NN, wmma::mem_row_major);
}

// ---------------------------------------------------------------------------
// K3 v2: scalar (neuron, channel) mapping -> every global LDG/STG is
// lane-consecutive (1-2 wavefronts/inst instead of 16). SMEM stride 8, no
// padding: lane addr = x*8+p covers 32 distinct banks; neighbor offsets are
// +-256/+-8 -> same pattern. 36KB smem -> 6 CTAs/SM.
// Two passes of 8 channels; per-neuron pep.action sum via 8-lane shfl
// reduction into sum_s, consumed by the final neuron-integration stage.
// ---------------------------------------------------------------------------
__global__ __launch_bounds__(256) void k_update(
    const float* __restrict__ state, const float* __restrict__ firing,
    const float* __restrict__ u, const float* __restrict__ D,
    const float* __restrict__ prod, const float* __restrict__ decay,
    const float* __restrict__ act, const float* __restrict__ ndecay,
    const float* __restrict__ input_layer, float* __restrict__ out_state)
{
    __shared__ float pep_s[NN * 8];   // 32KB: one 8-channel half, stride 8
    __shared__ float sum_s[NN];       // 4KB: per-neuron pep*act accumulator

    const int row = blockIdx.x;
    const int t = threadIdx.x;
    const size_t base = (size_t)row * SSTRIDE;
    const float* pep_g = state + base + PEP_OFF;
    float* outp = out_state + base + PEP_OFF;

    const int p  = t & 7;       // channel within half
    const int x0 = t >> 3;      // this thread's fixed x coordinate (0..31)

    #pragma unroll
    for (int pass = 0; pass < 2; pass++) {
        if (pass) __syncthreads();
        // Stage 8 channels: smem index == loop index (identity), fully coalesced
        for (int i = t; i < NN*8; i += 256)
            pep_s[i] = pep_g[(i >> 3)*NP + pass*8 + (i & 7)];
        __syncthreads();

        const float dd = fabsf(D[pass*8 + p]);
        const float pr = fabsf(prod[pass*8 + p]);
        const float de = fabsf(decay[pass*8 + p]);
        const float aa = act[pass*8 + p];

        #pragma unroll
        for (int j = 0; j < 32; j++) {          // j == y coordinate
            const int n  = j*32 + x0;
            const int yu = (j + 31) & 31, yd = (j + 1) & 31;
            const int xl = (x0 + 31) & 31, xr = (x0 + 1) & 31;
            const float c   = pep_s[n*8 + p];
            const float lap = pep_s[(yu*32 + x0)*8 + p]
                            + pep_s[(yd*32 + x0)*8 + p]
                            + pep_s[(j*32 + xl)*8 + p]
                            + pep_s[(j*32 + xr)*8 + p]
                            - 4.0f * c;
            const float fir = firing[row*NN + n];
            outp[n*NP + pass*8 + p] = c + DT_F*(pr*fir - de*c + dd*lap);
            float v = c * aa;                    // reduce over the 8-lane group
            v += __shfl_xor_sync(0xffffffffu, v, 1);
            v += __shfl_xor_sync(0xffffffffu, v, 2);
            v += __shfl_xor_sync(0xffffffffu, v, 4);
            if (p == 0) {
                if (pass == 0) sum_s[n] = v;
                else           sum_s[n] += v;
            }
        }
    }
    __syncthreads();

    // Neuron integration
    const float ndec = fabsf(ndecay[0]);
    const float uval = u[row];
    const float pc2  = state[base + PC2_OFF];
    #pragma unroll
    for (int k = 0; k < 4; k++) {
        const int n = t + k*256;
        const float ab = state[base + n];
        const float ne = state[base + NEU_OFF + n] * ab;
        const float dn = sum_s[n]*pc2 + g_dsyn[row*NN + n]
                       - ne*ndec + input_layer[n]*uval;
        out_state[base + NEU_OFF + n] = (ne + dn*DT_F) * ab;
    }
}

// ---------------------------------------------------------------------------
// Inputs (metadata order): u, state, noise_u, D, pep_prod_rate, pep_decay_rate,
// pep_action, synapse_matrix, neuron_decay, input_layer.
// Output: [firing (2048*1024) | state_new (2048*18433)] fp32.
// ---------------------------------------------------------------------------
extern "C" void kernel_launch(void* const* d_in, const int* in_sizes, int n_in,
                              void* d_out, int out_size)
{
    const float* u       = (const float*)d_in[0];
    const float* state   = (const float*)d_in[1];
    const float* noise_u = (const float*)d_in[2];
    const float* D       = (const float*)d_in[3];
    const float* prod    = (const float*)d_in[4];
    const float* decay   = (const float*)d_in[5];
    const float* act     = (const float*)d_in[6];
    const float* syn     = (const float*)d_in[7];
    const float* ndec    = (const float*)d_in[8];
    const float* inl     = (const float*)d_in[9];

    float* out        = (float*)d_out;
    float* out_firing = out;
    float* out_state  = out + (size_t)NBATCH*NN;

    k_cvt<<<(NN*NN/4)/256, 256>>>(syn);
    k_firing<<<(NBATCH*NN)/256, 256>>>(state, noise_u, out_firing, out_state);

    dim3 gg(NN/128, NBATCH/128);   // 8 x 16 CTAs
    k_gemm<<<gg, 256>>>();

    k_update<<<NBATCH, 256>>>(
        state, out_firing, u, D, prod, decay, act, ndec, inl, out_state);
}

// round 4
// speedup vs baseline: 1.5791x; 1.0492x over previous
#include <cuda_runtime.h>
#include <cuda_bf16.h>
#include <mma.h>
using namespace nvcuda;

#define NBATCH 2048
#define NN 1024
#define NP 16
#define SSTRIDE 18433        // 1024 ablate + 1 pc2 + 1024 neuron + 16384 peptide
#define PC2_OFF 1024
#define NEU_OFF 1025
#define PEP_OFF 2049
#define DT_F (1.0f/120.0f)

#define UPD_THREADS 512
#define UPD_SMEM ((NN*NP + NN) * 4)   // 64KB peptide + 4KB sums = 68KB dynamic

// Scratch (allocation-free rule: __device__ globals)
__device__ __nv_bfloat16 g_fir16[(size_t)NBATCH*NN];
__device__ __nv_bfloat16 g_syn16[(size_t)NN*NN];
__device__ float g_dsyn[(size_t)NBATCH*NN];

// ---------------------------------------------------------------------------
// K0: one-time synapse fp32 -> bf16
// ---------------------------------------------------------------------------
__global__ __launch_bounds__(256) void k_cvt(const float* __restrict__ syn)
{
    int i = blockIdx.x * 256 + threadIdx.x;          // NN*NN/4 threads
    float4 v = ((const float4*)syn)[i];
    __nv_bfloat162 lo = __floats2bfloat162_rn(v.x, v.y);
    __nv_bfloat162 hi = __floats2bfloat162_rn(v.z, v.w);
    ((__nv_bfloat162*)g_syn16)[i*2]     = lo;
    ((__nv_bfloat162*)g_syn16)[i*2 + 1] = hi;
}

// ---------------------------------------------------------------------------
// K1: firing = clip(-(relu(neuron)*ablate + 0.01)*log1p(-noise), 0, 10)
//     also emits bf16 copy for the GEMM and copies ablate/pc2 into state_new.
// ---------------------------------------------------------------------------
__global__ __launch_bounds__(256) void k_firing(
    const float* __restrict__ state, const float* __restrict__ noise_u,
    float* __restrict__ out_firing, float* __restrict__ out_state)
{
    int idx = blockIdx.x * 256 + threadIdx.x;   // exactly NBATCH*NN threads
    int row = idx >> 10;
    int n   = idx & (NN - 1);
    size_t base = (size_t)row * SSTRIDE;
    float ab    = state[base + n];
    float ne    = state[base + NEU_OFF + n];
    float noise = noise_u[idx];
    float f0  = fmaxf(ne, 0.0f) * ab;
    float fir = -(f0 + 0.01f) * log1pf(-noise);
    fir = fminf(fmaxf(fir, 0.0f), 10.0f);
    out_firing[idx] = fir;
    g_fir16[idx] = __float2bfloat16(fir);
    out_state[base + n] = ab;                       // ablate passthrough
    if (n == 0) out_state[base + PC2_OFF] = state[base + PC2_OFF];
}

// ---------------------------------------------------------------------------
// K2: g_dsyn[2048,1024] = firing_bf16 @ synapse_bf16
// 128x128x32 tiles, 8 warps (4x2), warp tile 32x64, register-prefetched
// double buffering of the next K tile during compute.
// ---------------------------------------------------------------------------
__global__ __launch_bounds__(256) void k_gemm()
{
    __shared__ __nv_bfloat16 As[128][48];
    __shared__ __nv_bfloat16 Bs[32][144];
    const int bm = blockIdx.y, bn = blockIdx.x;
    const int tid = threadIdx.x;
    const int wid = tid >> 5;
    const int wm = wid >> 1;
    const int wn = wid & 1;

    const int ar0 = (tid      ) >> 2, ac0 = (tid      ) & 3;
    const int ar1 = (tid + 256) >> 2, ac1 = (tid + 256) & 3;
    const int br0 = (tid      ) >> 4, bc0 = (tid      ) & 15;
    const int br1 = (tid + 256) >> 4, bc1 = (tid + 256) & 15;

    const __nv_bfloat16* Ag = g_fir16 + (size_t)bm*128*NN;
    const __nv_bfloat16* Bg = g_syn16 + bn*128;

    wmma::fragment<wmma::accumulator,16,16,16,float> acc[2][4];
    #pragma unroll
    for (int i = 0; i < 2; i++)
        #pragma unroll
        for (int j = 0; j < 4; j++) wmma::fill_fragment(acc[i][j], 0.0f);

    uint4 ra0, ra1, rb0, rb1;
    ra0 = *(const uint4*)(Ag + (size_t)ar0*NN + ac0*8);
    ra1 = *(const uint4*)(Ag + (size_t)ar1*NN + ac1*8);
    rb0 = *(const uint4*)(Bg + (size_t)br0*NN + bc0*8);
    rb1 = *(const uint4*)(Bg + (size_t)br1*NN + bc1*8);

    for (int k0 = 0; k0 < NN; k0 += 32) {
        *(uint4*)(&As[ar0][ac0*8]) = ra0;
        *(uint4*)(&As[ar1][ac1*8]) = ra1;
        *(uint4*)(&Bs[br0][bc0*8]) = rb0;
        *(uint4*)(&Bs[br1][bc1*8]) = rb1;
        __syncthreads();
        if (k0 + 32 < NN) {
            ra0 = *(const uint4*)(Ag + (size_t)ar0*NN + k0+32 + ac0*8);
            ra1 = *(const uint4*)(Ag + (size_t)ar1*NN + k0+32 + ac1*8);
            rb0 = *(const uint4*)(Bg + (size_t)(k0+32+br0)*NN + bc0*8);
            rb1 = *(const uint4*)(Bg + (size_t)(k0+32+br1)*NN + bc1*8);
        }
        #pragma unroll
        for (int kk = 0; kk < 32; kk += 16) {
            wmma::fragment<wmma::matrix_a,16,16,16,__nv_bfloat16,wmma::row_major> af[2];
            wmma::fragment<wmma::matrix_b,16,16,16,__nv_bfloat16,wmma::row_major> bf[4];
            #pragma unroll
            for (int i = 0; i < 2; i++)
                wmma::load_matrix_sync(af[i], &As[wm*32 + i*16][kk], 48);
            #pragma unroll
            for (int j = 0; j < 4; j++)
                wmma::load_matrix_sync(bf[j], &Bs[kk][wn*64 + j*16], 144);
            #pragma unroll
            for (int i = 0; i < 2; i++)
                #pragma unroll
                for (int j = 0; j < 4; j++)
                    wmma::mma_sync(acc[i][j], af[i], bf[j], acc[i][j]);
        }
        __syncthreads();
    }
    #pragma unroll
    for (int i = 0; i < 2; i++)
        #pragma unroll
        for (int j = 0; j < 4; j++)
            wmma::store_matrix_sync(
                g_dsyn + (size_t)(bm*128 + wm*32 + i*16)*NN + bn*128 + wn*64 + j*16,
                acc[i][j], NN, wmma::mem_row_major);
}

// ---------------------------------------------------------------------------
// K3 v3: SINGLE pass, 512 threads, full 64KB peptide row staged in dynamic
// smem. Thread map: p = t&15 (channel), x0 = t>>4 (x coord). Each j iteration
// a warp writes one contiguous 128B run (two neurons x 16 channels) -> full
// sector coverage, no DRAM read-modify-write. Smem stride 16 floats/neuron:
// the two 16-lane groups of a warp cover all 32 banks; stencil offsets are
// multiples of 16 floats -> conflict-free. 68KB smem -> 3 CTAs/SM (75% occ).
// ---------------------------------------------------------------------------
__global__ __launch_bounds__(UPD_THREADS) void k_update(
    const float* __restrict__ state, const float* __restrict__ firing,
    const float* __restrict__ u, const float* __restrict__ D,
    const float* __restrict__ prod, const float* __restrict__ decay,
    const float* __restrict__ act, const float* __restrict__ ndecay,
    const float* __restrict__ input_layer, float* __restrict__ out_state)
{
    extern __shared__ float sm[];
    float* pep_s = sm;            // NN*NP, stride NP per neuron
    float* sum_s = sm + NN*NP;    // NN per-neuron pep*act sums

    const int row = blockIdx.x;
    const int t = threadIdx.x;
    const size_t base = (size_t)row * SSTRIDE;
    const float* pep_g = state + base + PEP_OFF;
    float* outp = out_state + base + PEP_OFF;

    // Stage full peptide row: identity map, coalesced, 32 independent loads
    #pragma unroll 8
    for (int i = t; i < NN*NP; i += UPD_THREADS)
        pep_s[i] = pep_g[i];
    __syncthreads();

    const int p  = t & 15;      // peptide channel
    const int x0 = t >> 4;      // x coordinate (0..31)
    const float dd = fabsf(D[p]);
    const float pr = fabsf(prod[p]);
    const float de = fabsf(decay[p]);
    const float aa = act[p];

    #pragma unroll 4
    for (int j = 0; j < 32; j++) {          // j == y coordinate
        const int n  = j*32 + x0;
        const int yu = (j + 31) & 31, yd = (j + 1) & 31;
        const int xl = (x0 + 31) & 31, xr = (x0 + 1) & 31;
        const float c   = pep_s[n*NP + p];
        const float lap = pep_s[(yu*32 + x0)*NP + p]
                        + pep_s[(yd*32 + x0)*NP + p]
                        + pep_s[(j*32 + xl)*NP + p]
                        + pep_s[(j*32 + xr)*NP + p]
                        - 4.0f * c;
        const float fir = firing[row*NN + n];       // broadcast within 16-group
        outp[n*NP + p] = c + DT_F*(pr*fir - de*c + dd*lap);
        float v = c * aa;                   // reduce over the 16-lane group
        v += __shfl_xor_sync(0xffffffffu, v, 1);
        v += __shfl_xor_sync(0xffffffffu, v, 2);
        v += __shfl_xor_sync(0xffffffffu, v, 4);
        v += __shfl_xor_sync(0xffffffffu, v, 8);
        if (p == 0) sum_s[n] = v;
    }
    __syncthreads();

    // Neuron integration (512 threads x 2)
    const float ndec = fabsf(ndecay[0]);
    const float uval = u[row];
    const float pc2  = state[base + PC2_OFF];
    #pragma unroll
    for (int k = 0; k < 2; k++) {
        const int n = t + k*UPD_THREADS;
        const float ab = state[base + n];
        const float ne = state[base + NEU_OFF + n] * ab;
        const float dn = sum_s[n]*pc2 + g_dsyn[row*NN + n]
                       - ne*ndec + input_layer[n]*uval;
        out_state[base + NEU_OFF + n] = (ne + dn*DT_F) * ab;
    }
}

// ---------------------------------------------------------------------------
// Inputs (metadata order): u, state, noise_u, D, pep_prod_rate, pep_decay_rate,
// pep_action, synapse_matrix, neuron_decay, input_layer.
// Output: [firing (2048*1024) | state_new (2048*18433)] fp32.
// ---------------------------------------------------------------------------
extern "C" void kernel_launch(void* const* d_in, const int* in_sizes, int n_in,
                              void* d_out, int out_size)
{
    const float* u       = (const float*)d_in[0];
    const float* state   = (const float*)d_in[1];
    const float* noise_u = (const float*)d_in[2];
    const float* D       = (const float*)d_in[3];
    const float* prod    = (const float*)d_in[4];
    const float* decay   = (const float*)d_in[5];
    const float* act     = (const float*)d_in[6];
    const float* syn     = (const float*)d_in[7];
    const float* ndec    = (const float*)d_in[8];
    const float* inl     = (const float*)d_in[9];

    float* out        = (float*)d_out;
    float* out_firing = out;
    float* out_state  = out + (size_t)NBATCH*NN;

    // >48KB dynamic smem opt-in (sticky; not an allocation; capture-safe)
    cudaFuncSetAttribute(k_update, cudaFuncAttributeMaxDynamicSharedMemorySize,
                         UPD_SMEM);

    k_cvt<<<(NN*NN/4)/256, 256>>>(syn);
    k_firing<<<(NBATCH*NN)/256, 256>>>(state, noise_u, out_firing, out_state);

    dim3 gg(NN/128, NBATCH/128);   // 8 x 16 CTAs
    k_gemm<<<gg, 256>>>();

    k_update<<<NBATCH, UPD_THREADS, UPD_SMEM>>>(
        state, out_firing, u, D, prod, decay, act, ndec, inl, out_state);
}

// round 5
// speedup vs baseline: 1.8047x; 1.1429x over previous
#include <cuda_runtime.h>
#include <cuda_bf16.h>
#include <mma.h>
using namespace nvcuda;

#define NBATCH 2048
#define NN 1024
#define NP 16
#define SSTRIDE 18433        // 1024 ablate + 1 pc2 + 1024 neuron + 16384 peptide
#define PC2_OFF 1024
#define NEU_OFF 1025
#define PEP_OFF 2049
#define DT_F (1.0f/120.0f)

#define UPD_THREADS 512
#define UPD_SMEM (NN*NP*4)   // 64KB peptide stage

// Scratch (allocation-free rule: __device__ globals)
__device__ __nv_bfloat16 g_fir16[(size_t)NBATCH*NN];
__device__ __nv_bfloat16 g_syn16[(size_t)NN*NN];
__device__ float g_dsyn[(size_t)NBATCH*NN];

// ---------------------------------------------------------------------------
// K0: one-time synapse fp32 -> bf16
// ---------------------------------------------------------------------------
__global__ __launch_bounds__(256) void k_cvt(const float* __restrict__ syn)
{
    int i = blockIdx.x * 256 + threadIdx.x;          // NN*NN/4 threads
    float4 v = ((const float4*)syn)[i];
    __nv_bfloat162 lo = __floats2bfloat162_rn(v.x, v.y);
    __nv_bfloat162 hi = __floats2bfloat162_rn(v.z, v.w);
    ((__nv_bfloat162*)g_syn16)[i*2]     = lo;
    ((__nv_bfloat162*)g_syn16)[i*2 + 1] = hi;
}

// ---------------------------------------------------------------------------
// K1: firing = clip(-(relu(neuron)*ablate + 0.01)*log1p(-noise), 0, 10)
// ---------------------------------------------------------------------------
__global__ __launch_bounds__(256) void k_firing(
    const float* __restrict__ state, const float* __restrict__ noise_u,
    float* __restrict__ out_firing, float* __restrict__ out_state)
{
    int idx = blockIdx.x * 256 + threadIdx.x;   // exactly NBATCH*NN threads
    int row = idx >> 10;
    int n   = idx & (NN - 1);
    size_t base = (size_t)row * SSTRIDE;
    float ab    = state[base + n];
    float ne    = state[base + NEU_OFF + n];
    float noise = noise_u[idx];
    float f0  = fmaxf(ne, 0.0f) * ab;
    float fir = -(f0 + 0.01f) * log1pf(-noise);
    fir = fminf(fmaxf(fir, 0.0f), 10.0f);
    out_firing[idx] = fir;
    g_fir16[idx] = __float2bfloat16(fir);
    out_state[base + n] = ab;                       // ablate passthrough
    if (n == 0) out_state[base + PC2_OFF] = state[base + PC2_OFF];
}

// ---------------------------------------------------------------------------
// K2: g_dsyn = firing_bf16 @ synapse_bf16, 128x128x32 tiles, reg prefetch.
// ---------------------------------------------------------------------------
__global__ __launch_bounds__(256) void k_gemm()
{
    __shared__ __nv_bfloat16 As[128][48];
    __shared__ __nv_bfloat16 Bs[32][144];
    const int bm = blockIdx.y, bn = blockIdx.x;
    const int tid = threadIdx.x;
    const int wid = tid >> 5;
    const int wm = wid >> 1;
    const int wn = wid & 1;

    const int ar0 = (tid      ) >> 2, ac0 = (tid      ) & 3;
    const int ar1 = (tid + 256) >> 2, ac1 = (tid + 256) & 3;
    const int br0 = (tid      ) >> 4, bc0 = (tid      ) & 15;
    const int br1 = (tid + 256) >> 4, bc1 = (tid + 256) & 15;

    const __nv_bfloat16* Ag = g_fir16 + (size_t)bm*128*NN;
    const __nv_bfloat16* Bg = g_syn16 + bn*128;

    wmma::fragment<wmma::accumulator,16,16,16,float> acc[2][4];
    #pragma unroll
    for (int i = 0; i < 2; i++)
        #pragma unroll
        for (int j = 0; j < 4; j++) wmma::fill_fragment(acc[i][j], 0.0f);

    uint4 ra0, ra1, rb0, rb1;
    ra0 = *(const uint4*)(Ag + (size_t)ar0*NN + ac0*8);
    ra1 = *(const uint4*)(Ag + (size_t)ar1*NN + ac1*8);
    rb0 = *(const uint4*)(Bg + (size_t)br0*NN + bc0*8);
    rb1 = *(const uint4*)(Bg + (size_t)br1*NN + bc1*8);

    for (int k0 = 0; k0 < NN; k0 += 32) {
        *(uint4*)(&As[ar0][ac0*8]) = ra0;
        *(uint4*)(&As[ar1][ac1*8]) = ra1;
        *(uint4*)(&Bs[br0][bc0*8]) = rb0;
        *(uint4*)(&Bs[br1][bc1*8]) = rb1;
        __syncthreads();
        if (k0 + 32 < NN) {
            ra0 = *(const uint4*)(Ag + (size_t)ar0*NN + k0+32 + ac0*8);
            ra1 = *(const uint4*)(Ag + (size_t)ar1*NN + k0+32 + ac1*8);
            rb0 = *(const uint4*)(Bg + (size_t)(k0+32+br0)*NN + bc0*8);
            rb1 = *(const uint4*)(Bg + (size_t)(k0+32+br1)*NN + bc1*8);
        }
        #pragma unroll
        for (int kk = 0; kk < 32; kk += 16) {
            wmma::fragment<wmma::matrix_a,16,16,16,__nv_bfloat16,wmma::row_major> af[2];
            wmma::fragment<wmma::matrix_b,16,16,16,__nv_bfloat16,wmma::row_major> bf[4];
            #pragma unroll
            for (int i = 0; i < 2; i++)
                wmma::load_matrix_sync(af[i], &As[wm*32 + i*16][kk], 48);
            #pragma unroll
            for (int j = 0; j < 4; j++)
                wmma::load_matrix_sync(bf[j], &Bs[kk][wn*64 + j*16], 144);
            #pragma unroll
            for (int i = 0; i < 2; i++)
                #pragma unroll
                for (int j = 0; j < 4; j++)
                    wmma::mma_sync(acc[i][j], af[i], bf[j], acc[i][j]);
        }
        __syncthreads();
    }
    #pragma unroll
    for (int i = 0; i < 2; i++)
        #pragma unroll
        for (int j = 0; j < 4; j++)
            wmma::store_matrix_sync(
                g_dsyn + (size_t)(bm*128 + wm*32 + i*16)*NN + bn*128 + wn*64 + j*16,
                acc[i][j], NN, wmma::mem_row_major);
}

// ---------------------------------------------------------------------------
// K3 v4: single pass, 512 threads, 64KB peptide stage. NO shfl reduction:
// the per-neuron sum(pep*act) is recomputed in the neuron-integration phase
// with 4x LDS.128 dot products against act (pep_s still holds OLD values).
// Compute map: p = t&15 (channel), x0 = t>>4 (x) -> warp stores one
// contiguous 128B run per j (1 wavefront/STG).
// ---------------------------------------------------------------------------
__global__ __launch_bounds__(UPD_THREADS) void k_update(
    const float* __restrict__ state, const float* __restrict__ firing,
    const float* __restrict__ u, const float* __restrict__ D,
    const float* __restrict__ prod, const float* __restrict__ decay,
    const float* __restrict__ act, const float* __restrict__ ndecay,
    const float* __restrict__ input_layer, float* __restrict__ out_state)
{
    extern __shared__ float pep_s[];   // NN*NP, stride NP per neuron

    const int row = blockIdx.x;
    const int t = threadIdx.x;
    const size_t base = (size_t)row * SSTRIDE;
    const float* pep_g = state + base + PEP_OFF;
    float* outp = out_state + base + PEP_OFF;

    // Stage full peptide row: identity map, coalesced, deep MLP
    #pragma unroll 8
    for (int i = t; i < NN*NP; i += UPD_THREADS)
        pep_s[i] = pep_g[i];
    __syncthreads();

    const int p  = t & 15;      // peptide channel
    const int x0 = t >> 4;      // x coordinate (0..31)
    const float dd = fabsf(D[p]);
    const float pr = fabsf(prod[p]);
    const float de = fabsf(decay[p]);

    #pragma unroll 8
    for (int j = 0; j < 32; j++) {          // j == y coordinate
        const int n  = j*32 + x0;
        const int yu = (j + 31) & 31, yd = (j + 1) & 31;
        const int xl = (x0 + 31) & 31, xr = (x0 + 1) & 31;
        const float c   = pep_s[n*NP + p];
        const float lap = pep_s[(yu*32 + x0)*NP + p]
                        + pep_s[(yd*32 + x0)*NP + p]
                        + pep_s[(j*32 + xl)*NP + p]
                        + pep_s[(j*32 + xr)*NP + p]
                        - 4.0f * c;
        const float fir = firing[row*NN + n];   // 2 values/warp, L1 broadcast
        outp[n*NP + p] = c + DT_F*(pr*fir - de*c + dd*lap);
    }
    __syncthreads();

    // Neuron integration: pepsum recomputed from smem (old peptide values)
    const float ndec = fabsf(ndecay[0]);
    const float uval = u[row];
    const float pc2  = state[base + PC2_OFF];
    const float4 a0 = *(const float4*)(act);
    const float4 a1 = *(const float4*)(act + 4);
    const float4 a2 = *(const float4*)(act + 8);
    const float4 a3 = *(const float4*)(act + 12);
    #pragma unroll
    for (int k = 0; k < 2; k++) {
        const int n = t + k*UPD_THREADS;
        const float* P = pep_s + n*NP;
        const float4 c0 = *(const float4*)(P);
        const float4 c1 = *(const float4*)(P + 4);
        const float4 c2 = *(const float4*)(P + 8);
        const float4 c3 = *(const float4*)(P + 12);
        float pepsum = c0.x*a0.x + c0.y*a0.y + c0.z*a0.z + c0.w*a0.w
                     + c1.x*a1.x + c1.y*a1.y + c1.z*a1.z + c1.w*a1.w
                     + c2.x*a2.x + c2.y*a2.y + c2.z*a2.z + c2.w*a2.w
                     + c3.x*a3.x + c3.y*a3.y + c3.z*a3.z + c3.w*a3.w;
        const float ab = state[base + n];
        const float ne = state[base + NEU_OFF + n] * ab;
        const float dn = pepsum*pc2 + g_dsyn[row*NN + n]
                       - ne*ndec + input_layer[n]*uval;
        out_state[base + NEU_OFF + n] = (ne + dn*DT_F) * ab;
    }
}

// ---------------------------------------------------------------------------
// Inputs (metadata order): u, state, noise_u, D, pep_prod_rate, pep_decay_rate,
// pep_action, synapse_matrix, neuron_decay, input_layer.
// Output: [firing (2048*1024) | state_new (2048*18433)] fp32.
// ---------------------------------------------------------------------------
extern "C" void kernel_launch(void* const* d_in, const int* in_sizes, int n_in,
                              void* d_out, int out_size)
{
    const float* u       = (const float*)d_in[0];
    const float* state   = (const float*)d_in[1];
    const float* noise_u = (const float*)d_in[2];
    const float* D       = (const float*)d_in[3];
    const float* prod    = (const float*)d_in[4];
    const float* decay   = (const float*)d_in[5];
    const float* act     = (const float*)d_in[6];
    const float* syn     = (const float*)d_in[7];
    const float* ndec    = (const float*)d_in[8];
    const float* inl     = (const float*)d_in[9];

    float* out        = (float*)d_out;
    float* out_firing = out;
    float* out_state  = out + (size_t)NBATCH*NN;

    // >48KB dynamic smem opt-in (sticky; not an allocation; capture-safe)
    cudaFuncSetAttribute(k_update, cudaFuncAttributeMaxDynamicSharedMemorySize,
                         UPD_SMEM);

    k_cvt<<<(NN*NN/4)/256, 256>>>(syn);
    k_firing<<<(NBATCH*NN)/256, 256>>>(state, noise_u, out_firing, out_state);

    dim3 gg(NN/128, NBATCH/128);   // 8 x 16 CTAs
    k_gemm<<<gg, 256>>>();

    k_update<<<NBATCH, UPD_THREADS, UPD_SMEM>>>(
        state, out_firing, u, D, prod, decay, act, ndec, inl, out_state);
}